// round 10
// baseline (speedup 1.0000x reference)
#include <cuda_runtime.h>
#include <cuda_fp16.h>
#include <math.h>

// ---------------------------------------------------------------------------
// TriplaneEncoding, N=2^20 pts, levels r=128..1024, C=4.
// Line branch degenerates to per-(level,plane,channel) constants times
// (1 - |x2[p]|/2).  Planes re-stored as fp16 half4 texels in HORIZONTAL PAIRS
// at both parities:
//   even block: pair k=2j   -> (T[2j],   T[2j+1]),  j=0..r/2-1
//   odd  block: pair k=2j-1 -> (T[2j-1], T[2j]),    j=0..r/2 (zero pad ends)
// One LDG.128 fetches both u-corners (4 channels) for one row: 2 gathers
// per plane, 24 per point.
// Layout per (level l, plane p): [even: r*(r/2) uint4][odd: r*(r/2+1) uint4]
// Level bases (uint4): 0, 49536, 246912, 1034880; total 4,183,680 (67MB).
// Planes loaded with createpolicy(L2::evict_last) cache hints; output stored
// with .cs so the streaming output cannot evict the L2-resident planes.
// ---------------------------------------------------------------------------

__device__ uint4  g_planes[4183680];
__device__ float4 g_lineconst[12];

__device__ __forceinline__ __half2 h2(unsigned u) {
    union { unsigned u; __half2 h; } cv; cv.u = u; return cv.h;
}
__device__ __forceinline__ unsigned u32(__half2 h) {
    union { unsigned u; __half2 h; } cv; cv.h = h; return cv.u;
}
__device__ __forceinline__ unsigned long long mk_keep_policy() {
    unsigned long long pol;
    asm("createpolicy.fractional.L2::evict_last.b64 %0, 1.0;" : "=l"(pol));
    return pol;
}
__device__ __forceinline__ uint4 ldg_keep(const uint4* p, unsigned long long pol) {
    uint4 v;
    asm("ld.global.nc.L2::cache_hint.v4.u32 {%0,%1,%2,%3}, [%4], %5;"
        : "=r"(v.x), "=r"(v.y), "=r"(v.z), "=r"(v.w) : "l"(p), "l"(pol));
    return v;
}

// ---------------- convert: warp per 32-pair row segment ---------------------
// Each lane loads texels x=2j, 2j+1 (float2 per channel, coalesced, .cs),
// writes one even pair and one odd pair (odd first elem via shfl_up).
__global__ __launch_bounds__(256) void convert2_kernel(
    const float* __restrict__ p0, const float* __restrict__ p1,
    const float* __restrict__ p2, const float* __restrict__ p3) {
    const int LB[4] = {0, 49536, 246912, 1034880};
    int l = blockIdx.y;
    int r = 128 << l;
    int W = blockIdx.x * 8 + (threadIdx.x >> 5);
    int nW = 3 * r * (r >> 6);
    if (W >= nW) return;
    int lane = threadIdx.x & 31;
    int p   = W >> (8 + 2 * l);
    int rem = W & ((1 << (8 + 2 * l)) - 1);
    int y   = rem >> (1 + l);
    int seg = rem & ((1 << (1 + l)) - 1);
    int j = seg * 32 + lane;               // pair index in row, 0..r/2-1

    const float* src = (l == 0) ? p0 : (l == 1) ? p1 : (l == 2) ? p2 : p3;
    int rr = r * r;
    const float* rb = src + (size_t)p * 4 * rr + (size_t)y * r;

    float2 ch[4];
#pragma unroll
    for (int c = 0; c < 4; c++)
        ch[c] = __ldcs(reinterpret_cast<const float2*>(rb + c * rr + 2 * j));

    uint2 t0, t1;                          // texel 2j, texel 2j+1 (half4 each)
    t0.x = u32(__floats2half2_rn(ch[0].x, ch[1].x));
    t0.y = u32(__floats2half2_rn(ch[2].x, ch[3].x));
    t1.x = u32(__floats2half2_rn(ch[0].y, ch[1].y));
    t1.y = u32(__floats2half2_rn(ch[2].y, ch[3].y));

    int eb = LB[l] + p * r * (r + 1);
    int ob = eb + r * (r >> 1);
    int hp = (r >> 1) + 1;

    g_planes[eb + y * (r >> 1) + j] = make_uint4(t0.x, t0.y, t1.x, t1.y);

    uint2 pv;                              // texel 2j-1
    pv.x = __shfl_up_sync(0xffffffffu, t1.x, 1);
    pv.y = __shfl_up_sync(0xffffffffu, t1.y, 1);
    if (lane == 0) {
        if (j == 0) {
            pv = make_uint2(0u, 0u);
        } else {
            float a = __ldcs(rb + 0 * rr + 2 * j - 1);
            float b = __ldcs(rb + 1 * rr + 2 * j - 1);
            float c = __ldcs(rb + 2 * rr + 2 * j - 1);
            float d = __ldcs(rb + 3 * rr + 2 * j - 1);
            pv.x = u32(__floats2half2_rn(a, b));
            pv.y = u32(__floats2half2_rn(c, d));
        }
    }
    g_planes[ob + y * hp + j] = make_uint4(pv.x, pv.y, t0.x, t0.y);

    if (lane == 31 && seg == (r >> 6) - 1)  // trailing odd pair (T[r-1], 0)
        g_planes[ob + y * hp + (r >> 1)] = make_uint4(t1.x, t1.y, 0u, 0u);
}

// ---------------- line constants -------------------------------------------
__global__ void lineconst_kernel(const float* __restrict__ t0,
                                 const float* __restrict__ t1,
                                 const float* __restrict__ t2,
                                 const float* __restrict__ t3) {
    int t = threadIdx.x;
    if (t >= 48) return;
    int l = t / 12;
    int j = t % 12;
    const float* tl = (l == 0) ? t0 : (l == 1) ? t1 : (l == 2) ? t2 : t3;
    int r = 128 << l;
    float v = 0.5f * (__ldg(tl + j * r + r / 2 - 1) + __ldg(tl + j * r + r / 2));
    reinterpret_cast<float*>(g_lineconst)[t] = v;
}

// ---------------- main kernel ----------------------------------------------
// 128 pts/block. Results staged in smem (row pitch 133 f4 to spread banks),
// then written coalesced with st.global.cs (evict-first, protects planes).
__global__ __launch_bounds__(128) void tri_kernel(const float* __restrict__ xin,
                                                  float4* __restrict__ out4,
                                                  int N) {
    __shared__ float4 slc[12];
    __shared__ float4 sbuf[12 * 133];
    int tid = threadIdx.x;
    if (tid < 12) slc[tid] = g_lineconst[tid];
    __syncthreads();

    int i = blockIdx.x * 128 + tid;
    const int LB[4] = {0, 49536, 246912, 1034880};
    unsigned long long pol = mk_keep_policy();

    if (i < N) {
        float c[3], wl[3];
#pragma unroll
        for (int d = 0; d < 3; d++) {
            c[d] = fmaf(__ldg(xin + 3 * i + d), 2.f, -1.f);
            wl[d] = 1.f - 0.5f * fabsf(c[d]);
        }

#pragma unroll
        for (int l = 0; l < 4; l++) {
            const int r = 128 << l;
            const float hr = 0.5f * (float)r;

            int baseu[3], strideu[3], y0[3], y1[3];
            __half2 tuh[3], ty0h[3], ty1h[3];
#pragma unroll
            for (int d = 0; d < 3; d++) {
                float f = fmaf(c[d], hr, hr - 0.5f);
                float fl = floorf(f);
                float t = f - fl;
                int k = (int)fl;                  // in [-1, r-1]
                int par = k & 1;
                int col = (k + par) >> 1;
                strideu[d] = (r >> 1) + par;
                int eb = LB[l] + d * r * (r + 1); // plane d: u-axis = axis d
                baseu[d] = (par ? (eb + r * (r >> 1)) : eb) + col;
                tuh[d] = __float2half2_rn(t);
                y0[d] = max(k, 0);
                y1[d] = min(k + 1, r - 1);
                float s = wl[(d + 1) % 3];        // line weight of plane w/ v=d
                float w0 = (k >= 0) ? (1.f - t) * s : 0.f;
                float w1 = (k < r - 1) ? t * s : 0.f;
                ty0h[d] = __float2half2_rn(w0);
                ty1h[d] = __float2half2_rn(w1);
            }

#pragma unroll
            for (int p = 0; p < 3; p++) {
                const int ua = p;
                const int va = (p + 2) % 3;
                const uint4* q = g_planes + baseu[ua];
                int st = strideu[ua];
                uint4 A = ldg_keep(q + y0[va] * st, pol);
                uint4 B = ldg_keep(q + y1[va] * st, pol);
                __half2 tu = tuh[ua];
                __half2 xl0a = __hfma2(tu, __hsub2(h2(A.z), h2(A.x)), h2(A.x));
                __half2 xl0b = __hfma2(tu, __hsub2(h2(A.w), h2(A.y)), h2(A.y));
                __half2 xl1a = __hfma2(tu, __hsub2(h2(B.z), h2(B.x)), h2(B.x));
                __half2 xl1b = __hfma2(tu, __hsub2(h2(B.w), h2(B.y)), h2(B.y));
                __half2 yla = __hfma2(ty1h[va], xl1a, __hmul2(ty0h[va], xl0a));
                __half2 ylb = __hfma2(ty1h[va], xl1b, __hmul2(ty0h[va], xl0b));
                float2 fa = __half22float2(yla);
                float2 fb = __half22float2(ylb);
                float4 lc = slc[l * 3 + p];
                float4 o;
                o.x = fa.x * lc.x;
                o.y = fa.y * lc.y;
                o.z = fb.x * lc.z;
                o.w = fb.y * lc.w;
                sbuf[(l * 3 + p) * 133 + tid] = o;
            }
        }
    }
    __syncthreads();

    // Coalesced, evict-first output copy.
    size_t base = (size_t)blockIdx.x * 1536;     // 128 pts * 12 f4
    size_t lim = (size_t)N * 12;
#pragma unroll
    for (int k = 0; k < 12; k++) {
        int j = k * 128 + tid;
        if (base + j < lim) {
            float4 v = sbuf[(j % 12) * 133 + (j / 12)];
            __stcs(out4 + base + j, v);
        }
    }
}

// ---------------------------------------------------------------------------
extern "C" void kernel_launch(void* const* d_in, const int* in_sizes, int n_in,
                              void* d_out, int out_size) {
    const float* x = (const float*)d_in[0];
    const float* tp[4] = {nullptr, nullptr, nullptr, nullptr};
    const float* tl[4] = {nullptr, nullptr, nullptr, nullptr};

    for (int i = 1; i < n_in; i++) {
        int s = in_sizes[i];
        const float* ptr = (const float*)d_in[i];
        switch (s) {
            case 12 * 128 * 128:   tp[0] = ptr; break;
            case 12 * 256 * 256:   tp[1] = ptr; break;
            case 12 * 512 * 512:   tp[2] = ptr; break;
            case 12 * 1024 * 1024: tp[3] = ptr; break;
            case 12 * 128:         tl[0] = ptr; break;
            case 12 * 256:         tl[1] = ptr; break;
            case 12 * 512:         tl[2] = ptr; break;
            case 12 * 1024:        tl[3] = ptr; break;
            default: break;
        }
    }

    int N = in_sizes[0] / 3;

    // 1) convert into dual-parity fp16 pair layout (warp per row segment)
    dim3 cgrid(6144, 4);                     // 6144*8 warps covers level 3
    convert2_kernel<<<cgrid, 256>>>(tp[0], tp[1], tp[2], tp[3]);

    // 2) line constants
    lineconst_kernel<<<1, 64>>>(tl[0], tl[1], tl[2], tl[3]);

    // 3) main gather kernel
    tri_kernel<<<(N + 127) / 128, 128>>>(x, (float4*)d_out, N);
}

// round 11
// speedup vs baseline: 1.0029x; 1.0029x over previous
#include <cuda_runtime.h>
#include <cuda_fp16.h>
#include <math.h>

// ---------------------------------------------------------------------------
// TriplaneEncoding, N=2^20 pts, levels r=128..1024, C=4.
// Line branch degenerates to per-(level,plane,channel) constants times
// (1 - |x2[p]|/2).  Planes re-stored as fp16 half4 texels in HORIZONTAL PAIRS
// at both parities:
//   even block: pair k=2j   -> (T[2j],   T[2j+1]),  j=0..r/2-1
//   odd  block: pair k=2j-1 -> (T[2j-1], T[2j]),    j=0..r/2 (zero pad ends)
// One LDG.128 fetches both u-corners (4 channels) for one row: 2 gathers
// per plane, 24 per point.
// Layout per (level l, plane p): [even: r*(r/2) uint4][odd: r*(r/2+1) uint4]
// Level bases (uint4): 0, 49536, 246912, 1034880; total 4,183,680 (67MB).
// Gathers are plain __ldg (NO cache policy — evict_last hints regressed).
// Output staged in smem, then written coalesced with st.global.cs so the
// 192MB streaming output doesn't evict the L2-resident planes.
// ---------------------------------------------------------------------------

__device__ uint4  g_planes[4183680];
__device__ float4 g_lineconst[12];

__device__ __forceinline__ __half2 h2(unsigned u) {
    union { unsigned u; __half2 h; } cv; cv.u = u; return cv.h;
}
__device__ __forceinline__ unsigned u32(__half2 h) {
    union { unsigned u; __half2 h; } cv; cv.h = h; return cv.u;
}

// ---------------- convert: warp per 32-pair row segment ---------------------
__global__ __launch_bounds__(256) void convert2_kernel(
    const float* __restrict__ p0, const float* __restrict__ p1,
    const float* __restrict__ p2, const float* __restrict__ p3) {
    const int LB[4] = {0, 49536, 246912, 1034880};
    int l = blockIdx.y;
    int r = 128 << l;
    int W = blockIdx.x * 8 + (threadIdx.x >> 5);
    int nW = 3 * r * (r >> 6);
    if (W >= nW) return;
    int lane = threadIdx.x & 31;
    int p   = W >> (8 + 2 * l);
    int rem = W & ((1 << (8 + 2 * l)) - 1);
    int y   = rem >> (1 + l);
    int seg = rem & ((1 << (1 + l)) - 1);
    int j = seg * 32 + lane;               // pair index in row, 0..r/2-1

    const float* src = (l == 0) ? p0 : (l == 1) ? p1 : (l == 2) ? p2 : p3;
    int rr = r * r;
    const float* rb = src + (size_t)p * 4 * rr + (size_t)y * r;

    float2 ch[4];
#pragma unroll
    for (int c = 0; c < 4; c++)
        ch[c] = __ldcs(reinterpret_cast<const float2*>(rb + c * rr + 2 * j));

    uint2 t0, t1;                          // texel 2j, texel 2j+1 (half4 each)
    t0.x = u32(__floats2half2_rn(ch[0].x, ch[1].x));
    t0.y = u32(__floats2half2_rn(ch[2].x, ch[3].x));
    t1.x = u32(__floats2half2_rn(ch[0].y, ch[1].y));
    t1.y = u32(__floats2half2_rn(ch[2].y, ch[3].y));

    int eb = LB[l] + p * r * (r + 1);
    int ob = eb + r * (r >> 1);
    int hp = (r >> 1) + 1;

    g_planes[eb + y * (r >> 1) + j] = make_uint4(t0.x, t0.y, t1.x, t1.y);

    uint2 pv;                              // texel 2j-1
    pv.x = __shfl_up_sync(0xffffffffu, t1.x, 1);
    pv.y = __shfl_up_sync(0xffffffffu, t1.y, 1);
    if (lane == 0) {
        if (j == 0) {
            pv = make_uint2(0u, 0u);
        } else {
            float a = __ldcs(rb + 0 * rr + 2 * j - 1);
            float b = __ldcs(rb + 1 * rr + 2 * j - 1);
            float c = __ldcs(rb + 2 * rr + 2 * j - 1);
            float d = __ldcs(rb + 3 * rr + 2 * j - 1);
            pv.x = u32(__floats2half2_rn(a, b));
            pv.y = u32(__floats2half2_rn(c, d));
        }
    }
    g_planes[ob + y * hp + j] = make_uint4(pv.x, pv.y, t0.x, t0.y);

    if (lane == 31 && seg == (r >> 6) - 1)  // trailing odd pair (T[r-1], 0)
        g_planes[ob + y * hp + (r >> 1)] = make_uint4(t1.x, t1.y, 0u, 0u);
}

// ---------------- line constants -------------------------------------------
__global__ void lineconst_kernel(const float* __restrict__ t0,
                                 const float* __restrict__ t1,
                                 const float* __restrict__ t2,
                                 const float* __restrict__ t3) {
    int t = threadIdx.x;
    if (t >= 48) return;
    int l = t / 12;
    int j = t % 12;
    const float* tl = (l == 0) ? t0 : (l == 1) ? t1 : (l == 2) ? t2 : t3;
    int r = 128 << l;
    float v = 0.5f * (__ldg(tl + j * r + r / 2 - 1) + __ldg(tl + j * r + r / 2));
    reinterpret_cast<float*>(g_lineconst)[t] = v;
}

// ---------------- main kernel ----------------------------------------------
// 128 pts/block. Results staged in smem (row pitch 133 f4, conflict-free),
// then written coalesced with st.global.cs (evict-first, protects planes).
__global__ __launch_bounds__(128) void tri_kernel(const float* __restrict__ xin,
                                                  float4* __restrict__ out4,
                                                  int N) {
    __shared__ float4 slc[12];
    __shared__ float4 sbuf[12 * 133];
    int tid = threadIdx.x;
    if (tid < 12) slc[tid] = g_lineconst[tid];
    __syncthreads();

    int i = blockIdx.x * 128 + tid;
    const int LB[4] = {0, 49536, 246912, 1034880};

    if (i < N) {
        float c[3], wl[3];
#pragma unroll
        for (int d = 0; d < 3; d++) {
            c[d] = fmaf(__ldg(xin + 3 * i + d), 2.f, -1.f);
            wl[d] = 1.f - 0.5f * fabsf(c[d]);
        }

#pragma unroll
        for (int l = 0; l < 4; l++) {
            const int r = 128 << l;
            const float hr = 0.5f * (float)r;

            int baseu[3], strideu[3], y0[3], y1[3];
            __half2 tuh[3], ty0h[3], ty1h[3];
#pragma unroll
            for (int d = 0; d < 3; d++) {
                float f = fmaf(c[d], hr, hr - 0.5f);
                float fl = floorf(f);
                float t = f - fl;
                int k = (int)fl;                  // in [-1, r-1]
                int par = k & 1;
                int col = (k + par) >> 1;
                strideu[d] = (r >> 1) + par;
                int eb = LB[l] + d * r * (r + 1); // plane d: u-axis = axis d
                baseu[d] = (par ? (eb + r * (r >> 1)) : eb) + col;
                tuh[d] = __float2half2_rn(t);
                y0[d] = max(k, 0);
                y1[d] = min(k + 1, r - 1);
                float s = wl[(d + 1) % 3];        // line weight of plane w/ v=d
                float w0 = (k >= 0) ? (1.f - t) * s : 0.f;
                float w1 = (k < r - 1) ? t * s : 0.f;
                ty0h[d] = __float2half2_rn(w0);
                ty1h[d] = __float2half2_rn(w1);
            }

#pragma unroll
            for (int p = 0; p < 3; p++) {
                const int ua = p;
                const int va = (p + 2) % 3;
                const uint4* q = g_planes + baseu[ua];
                int st = strideu[ua];
                uint4 A = __ldg(q + y0[va] * st);
                uint4 B = __ldg(q + y1[va] * st);
                __half2 tu = tuh[ua];
                __half2 xl0a = __hfma2(tu, __hsub2(h2(A.z), h2(A.x)), h2(A.x));
                __half2 xl0b = __hfma2(tu, __hsub2(h2(A.w), h2(A.y)), h2(A.y));
                __half2 xl1a = __hfma2(tu, __hsub2(h2(B.z), h2(B.x)), h2(B.x));
                __half2 xl1b = __hfma2(tu, __hsub2(h2(B.w), h2(B.y)), h2(B.y));
                __half2 yla = __hfma2(ty1h[va], xl1a, __hmul2(ty0h[va], xl0a));
                __half2 ylb = __hfma2(ty1h[va], xl1b, __hmul2(ty0h[va], xl0b));
                float2 fa = __half22float2(yla);
                float2 fb = __half22float2(ylb);
                float4 lc = slc[l * 3 + p];
                float4 o;
                o.x = fa.x * lc.x;
                o.y = fa.y * lc.y;
                o.z = fb.x * lc.z;
                o.w = fb.y * lc.w;
                sbuf[(l * 3 + p) * 133 + tid] = o;
            }
        }
    }
    __syncthreads();

    // Coalesced, evict-first output copy.
    size_t base = (size_t)blockIdx.x * 1536;     // 128 pts * 12 f4
    size_t lim = (size_t)N * 12;
#pragma unroll
    for (int k = 0; k < 12; k++) {
        int j = k * 128 + tid;
        if (base + j < lim) {
            float4 v = sbuf[(j % 12) * 133 + (j / 12)];
            __stcs(out4 + base + j, v);
        }
    }
}

// ---------------------------------------------------------------------------
extern "C" void kernel_launch(void* const* d_in, const int* in_sizes, int n_in,
                              void* d_out, int out_size) {
    const float* x = (const float*)d_in[0];
    const float* tp[4] = {nullptr, nullptr, nullptr, nullptr};
    const float* tl[4] = {nullptr, nullptr, nullptr, nullptr};

    for (int i = 1; i < n_in; i++) {
        int s = in_sizes[i];
        const float* ptr = (const float*)d_in[i];
        switch (s) {
            case 12 * 128 * 128:   tp[0] = ptr; break;
            case 12 * 256 * 256:   tp[1] = ptr; break;
            case 12 * 512 * 512:   tp[2] = ptr; break;
            case 12 * 1024 * 1024: tp[3] = ptr; break;
            case 12 * 128:         tl[0] = ptr; break;
            case 12 * 256:         tl[1] = ptr; break;
            case 12 * 512:         tl[2] = ptr; break;
            case 12 * 1024:        tl[3] = ptr; break;
            default: break;
        }
    }

    int N = in_sizes[0] / 3;

    // 1) convert into dual-parity fp16 pair layout (warp per row segment)
    dim3 cgrid(6144, 4);                     // 6144*8 warps covers level 3
    convert2_kernel<<<cgrid, 256>>>(tp[0], tp[1], tp[2], tp[3]);

    // 2) line constants
    lineconst_kernel<<<1, 64>>>(tl[0], tl[1], tl[2], tl[3]);

    // 3) main gather kernel
    tri_kernel<<<(N + 127) / 128, 128>>>(x, (float4*)d_out, N);
}

// round 13
// speedup vs baseline: 1.5826x; 1.5780x over previous
#include <cuda_runtime.h>
#include <cuda_fp16.h>
#include <math.h>

// ---------------------------------------------------------------------------
// TriplaneEncoding, N=2^20 pts, levels r=128..1024, C=4.
// Line branch degenerates to per-(level,plane,channel) constants times
// (1 - |x2[p]|/2).  Planes re-stored as fp16 half4 texels in HORIZONTAL PAIRS
// at both parities:
//   even block: pair k=2j   -> (T[2j],   T[2j+1]),  j=0..r/2-1
//   odd  block: pair k=2j-1 -> (T[2j-1], T[2j]),    j=0..r/2 (zero pad ends)
// One LDG.128 fetches both u-corners (4 channels) for one row: 2 gathers
// per plane, 24 per point.
// Layout per (level l, plane p): [even: r*(r/2) uint4][odd: r*(r/2+1) uint4]
// Level bases (uint4): 0, 49536, 246912, 1034880; total 4,183,680 (67MB).
// Main kernel: R5 structure (256 thr/block, plain __ldg gathers, direct
// float4 stores) — staging/.cs experiments regressed and were reverted.
// ---------------------------------------------------------------------------

__device__ uint4  g_planes[4183680];
__device__ float4 g_lineconst[12];

__device__ __forceinline__ __half2 h2(unsigned u) {
    union { unsigned u; __half2 h; } cv; cv.u = u; return cv.h;
}
__device__ __forceinline__ unsigned u32(__half2 h) {
    union { unsigned u; __half2 h; } cv; cv.h = h; return cv.u;
}

// ---------------- convert: warp per 32-pair row segment ---------------------
__global__ __launch_bounds__(256) void convert2_kernel(
    const float* __restrict__ p0, const float* __restrict__ p1,
    const float* __restrict__ p2, const float* __restrict__ p3) {
    const int LB[4] = {0, 49536, 246912, 1034880};
    int l = blockIdx.y;
    int r = 128 << l;
    int W = blockIdx.x * 8 + (threadIdx.x >> 5);
    int nW = 3 * r * (r >> 6);
    if (W >= nW) return;
    int lane = threadIdx.x & 31;
    int p   = W >> (8 + 2 * l);
    int rem = W & ((1 << (8 + 2 * l)) - 1);
    int y   = rem >> (1 + l);
    int seg = rem & ((1 << (1 + l)) - 1);
    int j = seg * 32 + lane;               // pair index in row, 0..r/2-1

    const float* src = (l == 0) ? p0 : (l == 1) ? p1 : (l == 2) ? p2 : p3;
    int rr = r * r;
    const float* rb = src + (size_t)p * 4 * rr + (size_t)y * r;

    float2 ch[4];
#pragma unroll
    for (int c = 0; c < 4; c++)
        ch[c] = __ldcs(reinterpret_cast<const float2*>(rb + c * rr + 2 * j));

    uint2 t0, t1;                          // texel 2j, texel 2j+1 (half4 each)
    t0.x = u32(__floats2half2_rn(ch[0].x, ch[1].x));
    t0.y = u32(__floats2half2_rn(ch[2].x, ch[3].x));
    t1.x = u32(__floats2half2_rn(ch[0].y, ch[1].y));
    t1.y = u32(__floats2half2_rn(ch[2].y, ch[3].y));

    int eb = LB[l] + p * r * (r + 1);
    int ob = eb + r * (r >> 1);
    int hp = (r >> 1) + 1;

    g_planes[eb + y * (r >> 1) + j] = make_uint4(t0.x, t0.y, t1.x, t1.y);

    uint2 pv;                              // texel 2j-1
    pv.x = __shfl_up_sync(0xffffffffu, t1.x, 1);
    pv.y = __shfl_up_sync(0xffffffffu, t1.y, 1);
    if (lane == 0) {
        if (j == 0) {
            pv = make_uint2(0u, 0u);
        } else {
            float a = __ldcs(rb + 0 * rr + 2 * j - 1);
            float b = __ldcs(rb + 1 * rr + 2 * j - 1);
            float c = __ldcs(rb + 2 * rr + 2 * j - 1);
            float d = __ldcs(rb + 3 * rr + 2 * j - 1);
            pv.x = u32(__floats2half2_rn(a, b));
            pv.y = u32(__floats2half2_rn(c, d));
        }
    }
    g_planes[ob + y * hp + j] = make_uint4(pv.x, pv.y, t0.x, t0.y);

    if (lane == 31 && seg == (r >> 6) - 1)  // trailing odd pair (T[r-1], 0)
        g_planes[ob + y * hp + (r >> 1)] = make_uint4(t1.x, t1.y, 0u, 0u);
}

// ---------------- line constants -------------------------------------------
__global__ void lineconst_kernel(const float* __restrict__ t0,
                                 const float* __restrict__ t1,
                                 const float* __restrict__ t2,
                                 const float* __restrict__ t3) {
    int t = threadIdx.x;
    if (t >= 48) return;
    int l = t / 12;
    int j = t % 12;
    const float* tl = (l == 0) ? t0 : (l == 1) ? t1 : (l == 2) ? t2 : t3;
    int r = 128 << l;
    float v = 0.5f * (__ldg(tl + j * r + r / 2 - 1) + __ldg(tl + j * r + r / 2));
    reinterpret_cast<float*>(g_lineconst)[t] = v;
}

// ---------------- main kernel (R5 structure) --------------------------------
__global__ __launch_bounds__(256) void tri_kernel(const float* __restrict__ xin,
                                                  float* __restrict__ out,
                                                  int N) {
    __shared__ float4 slc[12];
    if (threadIdx.x < 12) slc[threadIdx.x] = g_lineconst[threadIdx.x];
    __syncthreads();

    int i = blockIdx.x * 256 + threadIdx.x;
    if (i >= N) return;

    float c[3], wl[3];
#pragma unroll
    for (int d = 0; d < 3; d++) {
        c[d] = fmaf(__ldg(xin + 3 * i + d), 2.f, -1.f);
        wl[d] = 1.f - 0.5f * fabsf(c[d]);
    }

    float4* op = reinterpret_cast<float4*>(out) + (size_t)i * 12;
    const int LB[4] = {0, 49536, 246912, 1034880};

#pragma unroll
    for (int l = 0; l < 4; l++) {
        const int r = 128 << l;
        const float hr = 0.5f * (float)r;

        int baseu[3], strideu[3], y0[3], y1[3];
        __half2 tuh[3], ty0h[3], ty1h[3];
#pragma unroll
        for (int d = 0; d < 3; d++) {
            float f = fmaf(c[d], hr, hr - 0.5f);
            float fl = floorf(f);
            float t = f - fl;
            int k = (int)fl;                    // in [-1, r-1]
            int par = k & 1;
            int col = (k + par) >> 1;
            strideu[d] = (r >> 1) + par;
            int eb = LB[l] + d * r * (r + 1);   // plane d: u-axis is axis d
            baseu[d] = (par ? (eb + r * (r >> 1)) : eb) + col;
            tuh[d] = __float2half2_rn(t);
            y0[d] = max(k, 0);
            y1[d] = min(k + 1, r - 1);
            // axis d is v-axis of plane (d+1)%3; fold its line weight in
            float s = wl[(d + 1) % 3];
            float w0 = (k >= 0) ? (1.f - t) * s : 0.f;   // zero-padding mask
            float w1 = (k < r - 1) ? t * s : 0.f;
            ty0h[d] = __float2half2_rn(w0);
            ty1h[d] = __float2half2_rn(w1);
        }

#pragma unroll
        for (int p = 0; p < 3; p++) {
            const int ua = p;
            const int va = (p + 2) % 3;
            const uint4* q = g_planes + baseu[ua];
            int st = strideu[ua];
            uint4 A = __ldg(q + y0[va] * st);   // row y0: (T0 | T1) half4 pair
            uint4 B = __ldg(q + y1[va] * st);   // row y1
            __half2 tu = tuh[ua];
            // x-lerp in fp16: v0 + t*(v1-v0)
            __half2 xl0a = __hfma2(tu, __hsub2(h2(A.z), h2(A.x)), h2(A.x));
            __half2 xl0b = __hfma2(tu, __hsub2(h2(A.w), h2(A.y)), h2(A.y));
            __half2 xl1a = __hfma2(tu, __hsub2(h2(B.z), h2(B.x)), h2(B.x));
            __half2 xl1b = __hfma2(tu, __hsub2(h2(B.w), h2(B.y)), h2(B.y));
            // y-lerp in fp16 (weights carry line-scale s)
            __half2 yla = __hfma2(ty1h[va], xl1a, __hmul2(ty0h[va], xl0a));
            __half2 ylb = __hfma2(ty1h[va], xl1b, __hmul2(ty0h[va], xl0b));
            float2 fa = __half22float2(yla);
            float2 fb = __half22float2(ylb);
            float4 lc = slc[l * 3 + p];
            float4 o;
            o.x = fa.x * lc.x;
            o.y = fa.y * lc.y;
            o.z = fb.x * lc.z;
            o.w = fb.y * lc.w;
            op[l * 3 + p] = o;
        }
    }
}

// ---------------------------------------------------------------------------
extern "C" void kernel_launch(void* const* d_in, const int* in_sizes, int n_in,
                              void* d_out, int out_size) {
    const float* x = (const float*)d_in[0];
    const float* tp[4] = {nullptr, nullptr, nullptr, nullptr};
    const float* tl[4] = {nullptr, nullptr, nullptr, nullptr};

    for (int i = 1; i < n_in; i++) {
        int s = in_sizes[i];
        const float* ptr = (const float*)d_in[i];
        switch (s) {
            case 12 * 128 * 128:   tp[0] = ptr; break;
            case 12 * 256 * 256:   tp[1] = ptr; break;
            case 12 * 512 * 512:   tp[2] = ptr; break;
            case 12 * 1024 * 1024: tp[3] = ptr; break;
            case 12 * 128:         tl[0] = ptr; break;
            case 12 * 256:         tl[1] = ptr; break;
            case 12 * 512:         tl[2] = ptr; break;
            case 12 * 1024:        tl[3] = ptr; break;
            default: break;
        }
    }

    int N = in_sizes[0] / 3;

    // 1) convert into dual-parity fp16 pair layout (warp per row segment)
    dim3 cgrid(6144, 4);                     // 6144*8 warps covers level 3
    convert2_kernel<<<cgrid, 256>>>(tp[0], tp[1], tp[2], tp[3]);

    // 2) line constants
    lineconst_kernel<<<1, 64>>>(tl[0], tl[1], tl[2], tl[3]);

    // 3) main gather kernel
    tri_kernel<<<(N + 255) / 256, 256>>>(x, (float*)d_out, N);
}

// round 15
// speedup vs baseline: 1.6289x; 1.0292x over previous
#include <cuda_runtime.h>
#include <cuda_fp16.h>
#include <math.h>

// ---------------------------------------------------------------------------
// TriplaneEncoding, N=2^20 pts, levels r=128..1024, C=4.
// Line branch degenerates to per-(level,plane,channel) constants times
// (1 - |x2[p]|/2).  Planes re-stored as fp16 half4 texels in HORIZONTAL PAIRS
// at both parities:
//   even block: pair k=2j   -> (T[2j],   T[2j+1]),  j=0..r/2-1
//   odd  block: pair k=2j-1 -> (T[2j-1], T[2j]),    j=0..r/2 (zero pad ends)
// One LDG.128 fetches both u-corners (4 channels) for one row: 2 gathers
// per plane, 24 per point.
// Layout per (level l, plane p): [even: r*(r/2) uint4][odd: r*(r/2+1) uint4]
// Level bases (uint4): 0, 49536, 246912, 1034880; total 4,183,680 (67MB).
// Main kernel: R5 structure (256 thr/block, plain __ldg gathers, direct
// float4 stores) + evict-first (.cs) output stores to protect L2 planes.
// ---------------------------------------------------------------------------

__device__ uint4  g_planes[4183680];
__device__ float4 g_lineconst[12];

__device__ __forceinline__ __half2 h2(unsigned u) {
    union { unsigned u; __half2 h; } cv; cv.u = u; return cv.h;
}
__device__ __forceinline__ unsigned u32(__half2 h) {
    union { unsigned u; __half2 h; } cv; cv.h = h; return cv.u;
}

// ---------------- convert (+lineconst): flat warp-indexed grid --------------
// Warp-block offsets per level (8 warps/block): level l owns flat blocks
// [CB[l], CB[l+1]).  nW(l) = 3*r*(r/64):  768, 3072, 12288, 49152 warps
// -> blocks: 96, 384, 1536, 6144 ; cumulative 0,96,480,2016,8160.
__global__ __launch_bounds__(256) void convert2_kernel(
    const float* __restrict__ p0, const float* __restrict__ p1,
    const float* __restrict__ p2, const float* __restrict__ p3,
    const float* __restrict__ l0, const float* __restrict__ l1,
    const float* __restrict__ l2, const float* __restrict__ l3) {
    const int LB[4] = {0, 49536, 246912, 1034880};

    // Fold the tiny lineconst computation into the first block.
    if (blockIdx.x == 0 && threadIdx.x < 48) {
        int t = threadIdx.x;
        int lv = t / 12;
        int j = t % 12;
        const float* tl = (lv == 0) ? l0 : (lv == 1) ? l1 : (lv == 2) ? l2 : l3;
        int r = 128 << lv;
        float v = 0.5f * (__ldg(tl + j * r + r / 2 - 1) + __ldg(tl + j * r + r / 2));
        reinterpret_cast<float*>(g_lineconst)[t] = v;
    }

    int b = blockIdx.x;
    int l = (b < 96) ? 0 : (b < 480) ? 1 : (b < 2016) ? 2 : 3;
    const int CB[4] = {0, 96, 480, 2016};
    int r = 128 << l;
    int W = (b - CB[l]) * 8 + (threadIdx.x >> 5);
    int lane = threadIdx.x & 31;
    int p   = W >> (8 + 2 * l);
    int rem = W & ((1 << (8 + 2 * l)) - 1);
    int y   = rem >> (1 + l);
    int seg = rem & ((1 << (1 + l)) - 1);
    int j = seg * 32 + lane;               // pair index in row, 0..r/2-1

    const float* src = (l == 0) ? p0 : (l == 1) ? p1 : (l == 2) ? p2 : p3;
    int rr = r * r;
    const float* rb = src + (size_t)p * 4 * rr + (size_t)y * r;

    float2 ch[4];
#pragma unroll
    for (int c = 0; c < 4; c++)
        ch[c] = __ldcs(reinterpret_cast<const float2*>(rb + c * rr + 2 * j));

    uint2 t0, t1;                          // texel 2j, texel 2j+1 (half4 each)
    t0.x = u32(__floats2half2_rn(ch[0].x, ch[1].x));
    t0.y = u32(__floats2half2_rn(ch[2].x, ch[3].x));
    t1.x = u32(__floats2half2_rn(ch[0].y, ch[1].y));
    t1.y = u32(__floats2half2_rn(ch[2].y, ch[3].y));

    int eb = LB[l] + p * r * (r + 1);
    int ob = eb + r * (r >> 1);
    int hp = (r >> 1) + 1;

    g_planes[eb + y * (r >> 1) + j] = make_uint4(t0.x, t0.y, t1.x, t1.y);

    uint2 pv;                              // texel 2j-1
    pv.x = __shfl_up_sync(0xffffffffu, t1.x, 1);
    pv.y = __shfl_up_sync(0xffffffffu, t1.y, 1);
    if (lane == 0) {
        if (j == 0) {
            pv = make_uint2(0u, 0u);
        } else {
            float a = __ldcs(rb + 0 * rr + 2 * j - 1);
            float b2 = __ldcs(rb + 1 * rr + 2 * j - 1);
            float c = __ldcs(rb + 2 * rr + 2 * j - 1);
            float d = __ldcs(rb + 3 * rr + 2 * j - 1);
            pv.x = u32(__floats2half2_rn(a, b2));
            pv.y = u32(__floats2half2_rn(c, d));
        }
    }
    g_planes[ob + y * hp + j] = make_uint4(pv.x, pv.y, t0.x, t0.y);

    if (lane == 31 && seg == (r >> 6) - 1)  // trailing odd pair (T[r-1], 0)
        g_planes[ob + y * hp + (r >> 1)] = make_uint4(t1.x, t1.y, 0u, 0u);
}

// ---------------- main kernel (R5 structure + .cs stores) -------------------
__global__ __launch_bounds__(256) void tri_kernel(const float* __restrict__ xin,
                                                  float* __restrict__ out,
                                                  int N) {
    __shared__ float4 slc[12];
    if (threadIdx.x < 12) slc[threadIdx.x] = g_lineconst[threadIdx.x];
    __syncthreads();

    int i = blockIdx.x * 256 + threadIdx.x;
    if (i >= N) return;

    float c[3], wl[3];
#pragma unroll
    for (int d = 0; d < 3; d++) {
        c[d] = fmaf(__ldg(xin + 3 * i + d), 2.f, -1.f);
        wl[d] = 1.f - 0.5f * fabsf(c[d]);
    }

    float4* op = reinterpret_cast<float4*>(out) + (size_t)i * 12;
    const int LB[4] = {0, 49536, 246912, 1034880};

#pragma unroll
    for (int l = 0; l < 4; l++) {
        const int r = 128 << l;
        const float hr = 0.5f * (float)r;

        int baseu[3], strideu[3], y0[3], y1[3];
        __half2 tuh[3], ty0h[3], ty1h[3];
#pragma unroll
        for (int d = 0; d < 3; d++) {
            float f = fmaf(c[d], hr, hr - 0.5f);
            float fl = floorf(f);
            float t = f - fl;
            int k = (int)fl;                    // in [-1, r-1]
            int par = k & 1;
            int col = (k + par) >> 1;
            strideu[d] = (r >> 1) + par;
            int eb = LB[l] + d * r * (r + 1);   // plane d: u-axis is axis d
            baseu[d] = (par ? (eb + r * (r >> 1)) : eb) + col;
            tuh[d] = __float2half2_rn(t);
            y0[d] = max(k, 0);
            y1[d] = min(k + 1, r - 1);
            // axis d is v-axis of plane (d+1)%3; fold its line weight in
            float s = wl[(d + 1) % 3];
            float w0 = (k >= 0) ? (1.f - t) * s : 0.f;   // zero-padding mask
            float w1 = (k < r - 1) ? t * s : 0.f;
            ty0h[d] = __float2half2_rn(w0);
            ty1h[d] = __float2half2_rn(w1);
        }

#pragma unroll
        for (int p = 0; p < 3; p++) {
            const int ua = p;
            const int va = (p + 2) % 3;
            const uint4* q = g_planes + baseu[ua];
            int st = strideu[ua];
            uint4 A = __ldg(q + y0[va] * st);   // row y0: (T0 | T1) half4 pair
            uint4 B = __ldg(q + y1[va] * st);   // row y1
            __half2 tu = tuh[ua];
            // x-lerp in fp16: v0 + t*(v1-v0)
            __half2 xl0a = __hfma2(tu, __hsub2(h2(A.z), h2(A.x)), h2(A.x));
            __half2 xl0b = __hfma2(tu, __hsub2(h2(A.w), h2(A.y)), h2(A.y));
            __half2 xl1a = __hfma2(tu, __hsub2(h2(B.z), h2(B.x)), h2(B.x));
            __half2 xl1b = __hfma2(tu, __hsub2(h2(B.w), h2(B.y)), h2(B.y));
            // y-lerp in fp16 (weights carry line-scale s)
            __half2 yla = __hfma2(ty1h[va], xl1a, __hmul2(ty0h[va], xl0a));
            __half2 ylb = __hfma2(ty1h[va], xl1b, __hmul2(ty0h[va], xl0b));
            float2 fa = __half22float2(yla);
            float2 fb = __half22float2(ylb);
            float4 lc = slc[l * 3 + p];
            float4 o;
            o.x = fa.x * lc.x;
            o.y = fa.y * lc.y;
            o.z = fb.x * lc.z;
            o.w = fb.y * lc.w;
            __stcs(op + l * 3 + p, o);          // evict-first: protect planes
        }
    }
}

// ---------------------------------------------------------------------------
extern "C" void kernel_launch(void* const* d_in, const int* in_sizes, int n_in,
                              void* d_out, int out_size) {
    const float* x = (const float*)d_in[0];
    const float* tp[4] = {nullptr, nullptr, nullptr, nullptr};
    const float* tl[4] = {nullptr, nullptr, nullptr, nullptr};

    for (int i = 1; i < n_in; i++) {
        int s = in_sizes[i];
        const float* ptr = (const float*)d_in[i];
        switch (s) {
            case 12 * 128 * 128:   tp[0] = ptr; break;
            case 12 * 256 * 256:   tp[1] = ptr; break;
            case 12 * 512 * 512:   tp[2] = ptr; break;
            case 12 * 1024 * 1024: tp[3] = ptr; break;
            case 12 * 128:         tl[0] = ptr; break;
            case 12 * 256:         tl[1] = ptr; break;
            case 12 * 512:         tl[2] = ptr; break;
            case 12 * 1024:        tl[3] = ptr; break;
            default: break;
        }
    }

    int N = in_sizes[0] / 3;

    // 1) convert into dual-parity fp16 pair layout (+ lineconst), flat grid
    convert2_kernel<<<8160, 256>>>(tp[0], tp[1], tp[2], tp[3],
                                   tl[0], tl[1], tl[2], tl[3]);

    // 2) main gather kernel
    tri_kernel<<<(N + 255) / 256, 256>>>(x, (float*)d_out, N);
}